// round 1
// baseline (speedup 1.0000x reference)
#include <cuda_runtime.h>

#define N_NODES 100000
#define N_EDGES 1600000
#define DIM 64
#define EPS 1e-5f

// ---- scratch (device globals; no allocation allowed) ----
__device__ __align__(16) float g_agg[N_NODES * DIM];   // scatter accumulator
__device__ __align__(16) float g_h2[N_NODES * DIM];    // post-GEMM activations
__device__ int   g_deg_out[N_NODES];
__device__ int   g_deg_in[N_NODES];
__device__ float g_norm_src[N_NODES];
__device__ float g_norm_dst[N_NODES];
__device__ float g_sum[DIM];
__device__ float g_sumsq[DIM];
__device__ float g_scale[DIM];
__device__ float g_shift[DIM];

// ---------------------------------------------------------------------------
// 1) degree histogram
// ---------------------------------------------------------------------------
__global__ void deg_kernel(const int* __restrict__ src,
                           const int* __restrict__ dst, int E) {
    int i = blockIdx.x * blockDim.x + threadIdx.x;
    if (i < E) {
        atomicAdd(&g_deg_out[src[i]], 1);
        atomicAdd(&g_deg_in[dst[i]], 1);
    }
}

// ---------------------------------------------------------------------------
// 2) norms: rsqrt(clamp(deg,1))
// ---------------------------------------------------------------------------
__global__ void norm_kernel(int n) {
    int i = blockIdx.x * blockDim.x + threadIdx.x;
    if (i < n) {
        int dout = g_deg_out[i]; if (dout < 1) dout = 1;
        int din  = g_deg_in[i];  if (din  < 1) din  = 1;
        g_norm_src[i] = rsqrtf((float)dout);
        g_norm_dst[i] = rsqrtf((float)din);
    }
}

// ---------------------------------------------------------------------------
// 3) edge scatter: agg[dst] += x[src] * norm_src[src]
//    16 threads per edge, one float4 vector-reduction each.
// ---------------------------------------------------------------------------
__global__ void scatter_kernel(const float4* __restrict__ x4,
                               const int* __restrict__ src,
                               const int* __restrict__ dst, int E) {
    int idx = blockIdx.x * blockDim.x + threadIdx.x;
    int e = idx >> 4;
    if (e >= E) return;
    int c = idx & 15;
    int s = __ldg(src + e);
    int d = __ldg(dst + e);
    float ns = __ldg(&g_norm_src[s]);
    float4 v = __ldg(x4 + (size_t)s * 16 + c);
    v.x *= ns; v.y *= ns; v.z *= ns; v.w *= ns;
    float* p = &g_agg[((size_t)d * 16 + c) * 4];
    asm volatile("red.global.add.v4.f32 [%0], {%1, %2, %3, %4};"
                 :: "l"(p), "f"(v.x), "f"(v.y), "f"(v.z), "f"(v.w)
                 : "memory");
}

// ---------------------------------------------------------------------------
// 4) GEMM: h2 = (agg * norm_dst) @ W + b, fused BN sum/sumsq accumulation.
//    64 rows/block, 256 threads (16x16), each thread a 4x4 output tile.
// ---------------------------------------------------------------------------
__global__ void gemm_bn_kernel(const float* __restrict__ W,
                               const float* __restrict__ b, int n) {
    __shared__ float Wsm[DIM * DIM];      // [k][j], row-major
    __shared__ float Asm[DIM][DIM + 1];   // [row][k], padded
    __shared__ float cs[DIM];
    __shared__ float css[DIM];

    int tid = threadIdx.x;
    int r0 = blockIdx.x * 64;

    // load W (4096 floats, 1024 float4)
    #pragma unroll
    for (int j = 0; j < 4; j++) {
        int i = tid + j * 256;
        ((float4*)Wsm)[i] = ((const float4*)W)[i];
    }
    // load A = agg rows * norm_dst, transposed-padded into smem
    #pragma unroll
    for (int j = 0; j < 4; j++) {
        int i = tid + j * 256;     // float4 index 0..1023
        int row = i >> 4;
        int c = i & 15;
        int gr = r0 + row;
        float4 v = make_float4(0.f, 0.f, 0.f, 0.f);
        if (gr < n) {
            v = ((const float4*)g_agg)[(size_t)gr * 16 + c];
            float nd = g_norm_dst[gr];
            v.x *= nd; v.y *= nd; v.z *= nd; v.w *= nd;
        }
        float* dp = &Asm[row][c * 4];
        dp[0] = v.x; dp[1] = v.y; dp[2] = v.z; dp[3] = v.w;
    }
    if (tid < DIM) { cs[tid] = 0.f; css[tid] = 0.f; }
    __syncthreads();

    int tx = tid & 15;   // col group: cols tx*4..tx*4+3
    int ty = tid >> 4;   // row group: rows ty*4..ty*4+3
    float acc[4][4] = {};

    #pragma unroll 8
    for (int k = 0; k < DIM; k++) {
        float4 w = ((const float4*)Wsm)[k * 16 + tx];
        float a0 = Asm[ty * 4 + 0][k];
        float a1 = Asm[ty * 4 + 1][k];
        float a2 = Asm[ty * 4 + 2][k];
        float a3 = Asm[ty * 4 + 3][k];
        acc[0][0] += a0 * w.x; acc[0][1] += a0 * w.y; acc[0][2] += a0 * w.z; acc[0][3] += a0 * w.w;
        acc[1][0] += a1 * w.x; acc[1][1] += a1 * w.y; acc[1][2] += a1 * w.z; acc[1][3] += a1 * w.w;
        acc[2][0] += a2 * w.x; acc[2][1] += a2 * w.y; acc[2][2] += a2 * w.z; acc[2][3] += a2 * w.w;
        acc[3][0] += a3 * w.x; acc[3][1] += a3 * w.y; acc[3][2] += a3 * w.z; acc[3][3] += a3 * w.w;
    }

    float4 bv = ((const float4*)b)[tx];
    float ps[4] = {0.f, 0.f, 0.f, 0.f};
    float pss[4] = {0.f, 0.f, 0.f, 0.f};
    #pragma unroll
    for (int i = 0; i < 4; i++) {
        int gr = r0 + ty * 4 + i;
        if (gr < n) {
            float4 o;
            o.x = acc[i][0] + bv.x;
            o.y = acc[i][1] + bv.y;
            o.z = acc[i][2] + bv.z;
            o.w = acc[i][3] + bv.w;
            ((float4*)g_h2)[(size_t)gr * 16 + tx] = o;
            ps[0] += o.x; pss[0] += o.x * o.x;
            ps[1] += o.y; pss[1] += o.y * o.y;
            ps[2] += o.z; pss[2] += o.z * o.z;
            ps[3] += o.w; pss[3] += o.w * o.w;
        }
    }
    #pragma unroll
    for (int j = 0; j < 4; j++) {
        atomicAdd(&cs[tx * 4 + j], ps[j]);
        atomicAdd(&css[tx * 4 + j], pss[j]);
    }
    __syncthreads();
    if (tid < DIM) {
        atomicAdd(&g_sum[tid], cs[tid]);
        atomicAdd(&g_sumsq[tid], css[tid]);
    }
}

// ---------------------------------------------------------------------------
// 5) BN finalize: per-column scale/shift
// ---------------------------------------------------------------------------
__global__ void bn_finalize_kernel(const float* __restrict__ gamma,
                                   const float* __restrict__ beta, int n) {
    int c = threadIdx.x;
    if (c < DIM) {
        float inv_n = 1.0f / (float)n;
        float mean = g_sum[c] * inv_n;
        float var = g_sumsq[c] * inv_n - mean * mean;
        float inv = rsqrtf(var + EPS);
        float sc = inv * gamma[c];
        g_scale[c] = sc;
        g_shift[c] = beta[c] - mean * sc;
    }
}

// ---------------------------------------------------------------------------
// 6) out = x + relu(h2*scale + shift)
// ---------------------------------------------------------------------------
__global__ void final_kernel(const float4* __restrict__ x4,
                             float4* __restrict__ out4, int n16) {
    int i = blockIdx.x * blockDim.x + threadIdx.x;
    if (i >= n16) return;
    int c = (i & 15) * 4;
    float4 h = ((const float4*)g_h2)[i];
    float4 xv = __ldg(x4 + i);
    float4 o;
    o.x = xv.x + fmaxf(h.x * g_scale[c + 0] + g_shift[c + 0], 0.f);
    o.y = xv.y + fmaxf(h.y * g_scale[c + 1] + g_shift[c + 1], 0.f);
    o.z = xv.z + fmaxf(h.z * g_scale[c + 2] + g_shift[c + 2], 0.f);
    o.w = xv.w + fmaxf(h.w * g_scale[c + 3] + g_shift[c + 3], 0.f);
    out4[i] = o;
}

// ---------------------------------------------------------------------------
extern "C" void kernel_launch(void* const* d_in, const int* in_sizes, int n_in,
                              void* d_out, int out_size) {
    const float* x     = (const float*)d_in[0];
    const int*   src   = (const int*)d_in[1];
    const int*   dst   = (const int*)d_in[2];
    const float* W     = (const float*)d_in[3];
    const float* b     = (const float*)d_in[4];
    const float* gamma = (const float*)d_in[5];
    const float* beta  = (const float*)d_in[6];

    int n = in_sizes[0] / DIM;   // 100000
    int e = in_sizes[1];         // 1600000

    void *p_agg, *p_do, *p_di, *p_s, *p_ss;
    cudaGetSymbolAddress(&p_agg, g_agg);
    cudaGetSymbolAddress(&p_do, g_deg_out);
    cudaGetSymbolAddress(&p_di, g_deg_in);
    cudaGetSymbolAddress(&p_s, g_sum);
    cudaGetSymbolAddress(&p_ss, g_sumsq);

    cudaMemsetAsync(p_agg, 0, (size_t)n * DIM * sizeof(float));
    cudaMemsetAsync(p_do, 0, (size_t)n * sizeof(int));
    cudaMemsetAsync(p_di, 0, (size_t)n * sizeof(int));
    cudaMemsetAsync(p_s, 0, DIM * sizeof(float));
    cudaMemsetAsync(p_ss, 0, DIM * sizeof(float));

    deg_kernel<<<(e + 255) / 256, 256>>>(src, dst, e);
    norm_kernel<<<(n + 255) / 256, 256>>>(n);

    long long sthreads = (long long)e * 16;
    scatter_kernel<<<(int)((sthreads + 255) / 256), 256>>>((const float4*)x, src, dst, e);

    gemm_bn_kernel<<<(n + 63) / 64, 256>>>(W, b, n);
    bn_finalize_kernel<<<1, 64>>>(gamma, beta, n);
    final_kernel<<<(n * 16 + 255) / 256, 256>>>((const float4*)x, (float4*)d_out, n * 16);
}

// round 2
// speedup vs baseline: 1.2732x; 1.2732x over previous
#include <cuda_runtime.h>

#define N_NODES 100000
#define N_EDGES 1600000
#define DIM 64
#define EPS 1e-5f
#define SCAN_B 512

// ---- scratch (device globals; no allocation allowed) ----
__device__ __align__(16) float g_agg[N_NODES * DIM];   // gathered features
__device__ __align__(16) float g_h2[N_NODES * DIM];    // post-GEMM activations
__device__ int   g_deg_out[N_NODES];
__device__ int   g_deg_in[N_NODES];
__device__ int   g_off[N_NODES];      // CSR row offsets (exclusive scan of deg_in)
__device__ int   g_fill[N_NODES];     // fill cursors
__device__ int   g_csr[N_EDGES];      // src indices grouped by dst
__device__ int   g_bsum[SCAN_B];      // per-block scan sums
__device__ int   g_boff[SCAN_B];
__device__ float g_norm_src[N_NODES];
__device__ float g_sum[DIM];
__device__ float g_sumsq[DIM];
__device__ float g_scale[DIM];
__device__ float g_shift[DIM];

// ---------------------------------------------------------------------------
// 1) degree histogram (both directions), 4 edges per thread via int4
// ---------------------------------------------------------------------------
__global__ void deg_kernel(const int4* __restrict__ src4,
                           const int4* __restrict__ dst4, int e4) {
    int i = blockIdx.x * blockDim.x + threadIdx.x;
    if (i < e4) {
        int4 s = __ldg(src4 + i);
        int4 d = __ldg(dst4 + i);
        atomicAdd(&g_deg_out[s.x], 1); atomicAdd(&g_deg_out[s.y], 1);
        atomicAdd(&g_deg_out[s.z], 1); atomicAdd(&g_deg_out[s.w], 1);
        atomicAdd(&g_deg_in[d.x], 1);  atomicAdd(&g_deg_in[d.y], 1);
        atomicAdd(&g_deg_in[d.z], 1);  atomicAdd(&g_deg_in[d.w], 1);
    }
}

// ---------------------------------------------------------------------------
// 2a) per-block exclusive scan of deg_in (512 elems/block)
// ---------------------------------------------------------------------------
__global__ void scanA_kernel(int n) {
    __shared__ int sm[SCAN_B];
    int t = threadIdx.x;
    int i = blockIdx.x * SCAN_B + t;
    int v = (i < n) ? g_deg_in[i] : 0;
    sm[t] = v;
    __syncthreads();
    #pragma unroll
    for (int off = 1; off < SCAN_B; off <<= 1) {
        int a = (t >= off) ? sm[t - off] : 0;
        __syncthreads();
        sm[t] += a;
        __syncthreads();
    }
    if (i < n) g_off[i] = sm[t] - v;           // exclusive
    if (t == SCAN_B - 1) g_bsum[blockIdx.x] = sm[t];
}

// ---------------------------------------------------------------------------
// 2b) scan of block sums (single block); also zero BN accumulators
// ---------------------------------------------------------------------------
__global__ void scanB_kernel(int nb) {
    __shared__ int sm[SCAN_B];
    int t = threadIdx.x;
    int v = (t < nb) ? g_bsum[t] : 0;
    sm[t] = v;
    __syncthreads();
    #pragma unroll
    for (int off = 1; off < SCAN_B; off <<= 1) {
        int a = (t >= off) ? sm[t - off] : 0;
        __syncthreads();
        sm[t] += a;
        __syncthreads();
    }
    if (t < nb) g_boff[t] = sm[t] - v;
    if (t < DIM) { g_sum[t] = 0.f; g_sumsq[t] = 0.f; }
}

// ---------------------------------------------------------------------------
// 2c) finalize offsets + fill cursors + norm_src
// ---------------------------------------------------------------------------
__global__ void scanC_kernel(int n) {
    int i = blockIdx.x * blockDim.x + threadIdx.x;
    if (i < n) {
        int off = g_off[i] + g_boff[i >> 9];
        g_off[i] = off;
        g_fill[i] = off;
        int d = g_deg_out[i];
        g_norm_src[i] = rsqrtf((float)(d < 1 ? 1 : d));
    }
}

// ---------------------------------------------------------------------------
// 3) CSR bucket fill: group src indices by dst
// ---------------------------------------------------------------------------
__global__ void fill_kernel(const int* __restrict__ src,
                            const int* __restrict__ dst, int E) {
    int i = blockIdx.x * blockDim.x + threadIdx.x;
    if (i < E) {
        int d = __ldg(dst + i);
        int p = atomicAdd(&g_fill[d], 1);
        g_csr[p] = __ldg(src + i);
    }
}

// ---------------------------------------------------------------------------
// 4) gather: agg[v] = norm_dst[v] * sum_{s in in(v)} norm_src[s] * x[s]
//    half-warp (16 lanes) per node, lane c owns float4 column chunk c.
// ---------------------------------------------------------------------------
__global__ void gather_kernel(const float4* __restrict__ x4, int n) {
    int tid = threadIdx.x;
    int node = blockIdx.x * 16 + (tid >> 4);
    if (node >= n) return;
    int c = tid & 15;
    int start = g_off[node];
    int deg = g_deg_in[node];

    float4 acc = make_float4(0.f, 0.f, 0.f, 0.f);
    #pragma unroll 2
    for (int j = 0; j < deg; j++) {
        int s = __ldg(&g_csr[start + j]);
        float ns = __ldg(&g_norm_src[s]);
        float4 v = __ldg(x4 + (size_t)s * 16 + c);
        acc.x += ns * v.x; acc.y += ns * v.y;
        acc.z += ns * v.z; acc.w += ns * v.w;
    }
    float nd = rsqrtf((float)(deg < 1 ? 1 : deg));
    acc.x *= nd; acc.y *= nd; acc.z *= nd; acc.w *= nd;
    ((float4*)g_agg)[(size_t)node * 16 + c] = acc;
}

// ---------------------------------------------------------------------------
// 5) GEMM: h2 = agg @ W + b, fused BN sum/sumsq accumulation.
//    64 rows/block, 256 threads (16x16), each thread a 4x4 output tile.
// ---------------------------------------------------------------------------
__global__ void gemm_bn_kernel(const float* __restrict__ W,
                               const float* __restrict__ b, int n) {
    __shared__ float Wsm[DIM * DIM];      // [k][j], row-major
    __shared__ float Asm[DIM][DIM + 1];   // [row][k], padded
    __shared__ float cs[DIM];
    __shared__ float css[DIM];

    int tid = threadIdx.x;
    int r0 = blockIdx.x * 64;

    #pragma unroll
    for (int j = 0; j < 4; j++) {
        int i = tid + j * 256;
        ((float4*)Wsm)[i] = ((const float4*)W)[i];
    }
    #pragma unroll
    for (int j = 0; j < 4; j++) {
        int i = tid + j * 256;     // float4 index 0..1023
        int row = i >> 4;
        int c = i & 15;
        int gr = r0 + row;
        float4 v = make_float4(0.f, 0.f, 0.f, 0.f);
        if (gr < n) v = ((const float4*)g_agg)[(size_t)gr * 16 + c];
        float* dp = &Asm[row][c * 4];
        dp[0] = v.x; dp[1] = v.y; dp[2] = v.z; dp[3] = v.w;
    }
    if (tid < DIM) { cs[tid] = 0.f; css[tid] = 0.f; }
    __syncthreads();

    int tx = tid & 15;
    int ty = tid >> 4;
    float acc[4][4] = {};

    #pragma unroll 8
    for (int k = 0; k < DIM; k++) {
        float4 w = ((const float4*)Wsm)[k * 16 + tx];
        float a0 = Asm[ty * 4 + 0][k];
        float a1 = Asm[ty * 4 + 1][k];
        float a2 = Asm[ty * 4 + 2][k];
        float a3 = Asm[ty * 4 + 3][k];
        acc[0][0] += a0 * w.x; acc[0][1] += a0 * w.y; acc[0][2] += a0 * w.z; acc[0][3] += a0 * w.w;
        acc[1][0] += a1 * w.x; acc[1][1] += a1 * w.y; acc[1][2] += a1 * w.z; acc[1][3] += a1 * w.w;
        acc[2][0] += a2 * w.x; acc[2][1] += a2 * w.y; acc[2][2] += a2 * w.z; acc[2][3] += a2 * w.w;
        acc[3][0] += a3 * w.x; acc[3][1] += a3 * w.y; acc[3][2] += a3 * w.z; acc[3][3] += a3 * w.w;
    }

    float4 bv = ((const float4*)b)[tx];
    float ps[4] = {0.f, 0.f, 0.f, 0.f};
    float pss[4] = {0.f, 0.f, 0.f, 0.f};
    #pragma unroll
    for (int i = 0; i < 4; i++) {
        int gr = r0 + ty * 4 + i;
        if (gr < n) {
            float4 o;
            o.x = acc[i][0] + bv.x;
            o.y = acc[i][1] + bv.y;
            o.z = acc[i][2] + bv.z;
            o.w = acc[i][3] + bv.w;
            ((float4*)g_h2)[(size_t)gr * 16 + tx] = o;
            ps[0] += o.x; pss[0] += o.x * o.x;
            ps[1] += o.y; pss[1] += o.y * o.y;
            ps[2] += o.z; pss[2] += o.z * o.z;
            ps[3] += o.w; pss[3] += o.w * o.w;
        }
    }
    #pragma unroll
    for (int j = 0; j < 4; j++) {
        atomicAdd(&cs[tx * 4 + j], ps[j]);
        atomicAdd(&css[tx * 4 + j], pss[j]);
    }
    __syncthreads();
    if (tid < DIM) {
        atomicAdd(&g_sum[tid], cs[tid]);
        atomicAdd(&g_sumsq[tid], css[tid]);
    }
}

// ---------------------------------------------------------------------------
// 6) BN finalize: per-column scale/shift
// ---------------------------------------------------------------------------
__global__ void bn_finalize_kernel(const float* __restrict__ gamma,
                                   const float* __restrict__ beta, int n) {
    int c = threadIdx.x;
    if (c < DIM) {
        float inv_n = 1.0f / (float)n;
        float mean = g_sum[c] * inv_n;
        float var = g_sumsq[c] * inv_n - mean * mean;
        float inv = rsqrtf(var + EPS);
        float sc = inv * gamma[c];
        g_scale[c] = sc;
        g_shift[c] = beta[c] - mean * sc;
    }
}

// ---------------------------------------------------------------------------
// 7) out = x + relu(h2*scale + shift)
// ---------------------------------------------------------------------------
__global__ void final_kernel(const float4* __restrict__ x4,
                             float4* __restrict__ out4, int n16) {
    int i = blockIdx.x * blockDim.x + threadIdx.x;
    if (i >= n16) return;
    int c = (i & 15) * 4;
    float4 h = ((const float4*)g_h2)[i];
    float4 xv = __ldg(x4 + i);
    float4 o;
    o.x = xv.x + fmaxf(h.x * g_scale[c + 0] + g_shift[c + 0], 0.f);
    o.y = xv.y + fmaxf(h.y * g_scale[c + 1] + g_shift[c + 1], 0.f);
    o.z = xv.z + fmaxf(h.z * g_scale[c + 2] + g_shift[c + 2], 0.f);
    o.w = xv.w + fmaxf(h.w * g_scale[c + 3] + g_shift[c + 3], 0.f);
    out4[i] = o;
}

// ---------------------------------------------------------------------------
extern "C" void kernel_launch(void* const* d_in, const int* in_sizes, int n_in,
                              void* d_out, int out_size) {
    const float* x     = (const float*)d_in[0];
    const int*   src   = (const int*)d_in[1];
    const int*   dst   = (const int*)d_in[2];
    const float* W     = (const float*)d_in[3];
    const float* b     = (const float*)d_in[4];
    const float* gamma = (const float*)d_in[5];
    const float* beta  = (const float*)d_in[6];

    int n = in_sizes[0] / DIM;   // 100000
    int e = in_sizes[1];         // 1600000

    void *p_do, *p_di;
    cudaGetSymbolAddress(&p_do, g_deg_out);
    cudaGetSymbolAddress(&p_di, g_deg_in);
    cudaMemsetAsync(p_do, 0, (size_t)n * sizeof(int));
    cudaMemsetAsync(p_di, 0, (size_t)n * sizeof(int));

    int e4 = e / 4;  // E is a multiple of 4
    deg_kernel<<<(e4 + 255) / 256, 256>>>((const int4*)src, (const int4*)dst, e4);

    int nb = (n + SCAN_B - 1) / SCAN_B;       // 196
    scanA_kernel<<<nb, SCAN_B>>>(n);
    scanB_kernel<<<1, SCAN_B>>>(nb);
    scanC_kernel<<<(n + 255) / 256, 256>>>(n);

    fill_kernel<<<(e + 255) / 256, 256>>>(src, dst, e);

    gather_kernel<<<(n + 15) / 16, 256>>>((const float4*)x, n);

    gemm_bn_kernel<<<(n + 63) / 64, 256>>>(W, b, n);
    bn_finalize_kernel<<<1, 64>>>(gamma, beta, n);
    final_kernel<<<(n * 16 + 255) / 256, 256>>>((const float4*)x, (float4*)d_out, n * 16);
}